// round 16
// baseline (speedup 1.0000x reference)
#include <cuda_runtime.h>
#include <cuda_fp16.h>
#include <math.h>
#include <stdint.h>

// Problem constants (fixed shapes from reference)
#define SEQ   2048
#define HID   2048
#define NHEAD 16
#define HDIM  128
#define QKV_N (3 * HID)   // 6144

// -------- device scratch (static; no allocations allowed) --------
__device__ __half g_qkv[SEQ * QKV_N];     // [s, 3h] QKV output (fp16)
__device__ __half g_ctx[SEQ * HID];       // [s, h] context (fp16)
__device__ __half g_hs[SEQ * HID];        // fp16 hidden_states
__device__ __half g_wqkv[QKV_N * HID];    // fp16 w_qkv
__device__ __half g_wproj[HID * HID];     // fp16 w_proj
__device__ int    g_mflag[16 * 16];       // per-128x128-tile mask OR flags

// ---------------------------------------------------------------------------
// helpers
// ---------------------------------------------------------------------------
__device__ __forceinline__ uint32_t pack_h2(float lo, float hi) {
    __half2 h = __floats2half2_rn(lo, hi);
    return *reinterpret_cast<uint32_t*>(&h);
}

__device__ __forceinline__ uint32_t ex2_h2(float lo, float hi) {
    __half2 h = __floats2half2_rn(lo, hi);
    uint32_t x = *reinterpret_cast<uint32_t*>(&h);
    uint32_t r;
    asm("ex2.approx.f16x2 %0, %1;" : "=r"(r) : "r"(x));
    return r;
}

__device__ __forceinline__ void mma_f16(float* d, const uint32_t* a, const uint32_t* b) {
    asm volatile(
        "mma.sync.aligned.m16n8k16.row.col.f32.f16.f16.f32 "
        "{%0,%1,%2,%3}, {%4,%5,%6,%7}, {%8,%9}, {%0,%1,%2,%3};"
        : "+f"(d[0]), "+f"(d[1]), "+f"(d[2]), "+f"(d[3])
        : "r"(a[0]), "r"(a[1]), "r"(a[2]), "r"(a[3]), "r"(b[0]), "r"(b[1]));
}

__device__ __forceinline__ void ldsm_x4(uint32_t* r, const void* p) {
    uint32_t a = (uint32_t)__cvta_generic_to_shared(p);
    asm volatile("ldmatrix.sync.aligned.m8n8.x4.shared.b16 {%0,%1,%2,%3}, [%4];"
        : "=r"(r[0]), "=r"(r[1]), "=r"(r[2]), "=r"(r[3]) : "r"(a));
}

__device__ __forceinline__ void ldsm_x4_t(uint32_t* r, const void* p) {
    uint32_t a = (uint32_t)__cvta_generic_to_shared(p);
    asm volatile("ldmatrix.sync.aligned.m8n8.x4.trans.shared.b16 {%0,%1,%2,%3}, [%4];"
        : "=r"(r[0]), "=r"(r[1]), "=r"(r[2]), "=r"(r[3]) : "r"(a));
}

__device__ __forceinline__ void cp16(void* dst_smem, const void* src) {
    uint32_t d = (uint32_t)__cvta_generic_to_shared(dst_smem);
    asm volatile("cp.async.cg.shared.global [%0], [%1], 16;" :: "r"(d), "l"(src));
}
#define CP_COMMIT() asm volatile("cp.async.commit_group;" ::: "memory")
#define CP_WAIT(N)  asm volatile("cp.async.wait_group %0;" :: "n"(N) : "memory")

// ---------------------------------------------------------------------------
// fp32 -> fp16 conversion, MLP=4
// ---------------------------------------------------------------------------
__global__ void __launch_bounds__(256)
prep_h(const float* __restrict__ src, __half* __restrict__ dst, int n4)
{
    int base = blockIdx.x * 1024 + threadIdx.x;
    float4 v[4];
    #pragma unroll
    for (int i = 0; i < 4; i++) {
        int idx = base + i * 256;
        if (idx < n4) v[i] = ((const float4*)src)[idx];
    }
    #pragma unroll
    for (int i = 0; i < 4; i++) {
        int idx = base + i * 256;
        if (idx < n4)
            ((uint2*)dst)[idx] = make_uint2(pack_h2(v[i].x, v[i].y),
                                            pack_h2(v[i].z, v[i].w));
    }
}

// ---------------------------------------------------------------------------
// mask tile OR-reduction
// ---------------------------------------------------------------------------
__global__ void __launch_bounds__(256)
mask_reduce(const uint8_t* __restrict__ mask)
{
    const int qt = blockIdx.y, kt = blockIdx.x;
    const uint8_t* base = mask + (size_t)(qt * 128) * SEQ + kt * 128;
    uint32_t acc = 0;
    #pragma unroll
    for (int i = 0; i < 4; i++) {
        int idx = threadIdx.x + i * 256;
        int r = idx >> 3, c = (idx & 7) * 16;
        uint4 v = *(const uint4*)(base + (size_t)r * SEQ + c);
        acc |= v.x | v.y | v.z | v.w;
    }
    int any = __syncthreads_or((int)(acc != 0));
    if (threadIdx.x == 0) g_mflag[qt * 16 + kt] = any;
}

// ---------------------------------------------------------------------------
// fp16 mma.sync GEMM (round-7 config, best known)
// ---------------------------------------------------------------------------
#define HSM 72
#define GSTG 3
#define GEMM_SMEM (GSTG * 2 * 128 * HSM * 2)   // 110592 bytes

template<bool OUT_HALF>
__global__ void __launch_bounds__(256, 2)
gemm_h(const __half* __restrict__ A, int lda,
       const __half* __restrict__ B, int ldb,
       void* __restrict__ Cv, int ldc,
       const float* __restrict__ bias, int K)
{
    extern __shared__ __half smh[];
    __half* As = smh;
    __half* Bs = smh + GSTG * 128 * HSM;

    const int tid = threadIdx.x;
    const int wid = tid >> 5;
    const int lane = tid & 31;
    const int t = lane & 3;
    const int g = lane >> 2;
    const int wm = wid & 1;
    const int wn = wid >> 1;

    A += (size_t)(blockIdx.y * 128) * lda;
    B += (size_t)(blockIdx.x * 128) * ldb;

    float acc[4][4][4];
    #pragma unroll
    for (int mi = 0; mi < 4; mi++)
        #pragma unroll
        for (int ni = 0; ni < 4; ni++)
            #pragma unroll
            for (int q = 0; q < 4; q++) acc[mi][ni][q] = 0.0f;

    const int nch = K >> 6;

    auto issue = [&](int st, int k0) {
        __half* as = As + st * 128 * HSM;
        __half* bs = Bs + st * 128 * HSM;
        #pragma unroll
        for (int i = 0; i < 4; i++) {
            int idx = tid + i * 256;
            int r = idx >> 3;
            int sgo = (idx & 7) * 8;
            cp16(as + r * HSM + sgo, A + (size_t)r * lda + k0 + sgo);
            cp16(bs + r * HSM + sgo, B + (size_t)r * ldb + k0 + sgo);
        }
        CP_COMMIT();
    };

    issue(0, 0);
    if (nch > 1) issue(1, 64);

    const int a_row = wm * 64 + (lane & 15);
    const int a_col = (lane >> 4) << 3;
    const int b_row = wn * 32 + ((lane >> 4) << 3) + (lane & 7);
    const int b_col = ((lane >> 3) & 1) << 3;

    for (int c = 0; c < nch; c++) {
        if (c + 1 < nch) { CP_WAIT(1); } else { CP_WAIT(0); }
        __syncthreads();
        if (c + 2 < nch) issue((c + 2) % GSTG, (c + 2) * 64);

        const __half* as = As + (c % GSTG) * 128 * HSM;
        const __half* bs = Bs + (c % GSTG) * 128 * HSM;
        #pragma unroll
        for (int ks = 0; ks < 4; ks++) {
            uint32_t af[4][4], bf[2][4];
            #pragma unroll
            for (int mi = 0; mi < 4; mi++)
                ldsm_x4(af[mi], as + (size_t)(a_row + mi * 16) * HSM + ks * 16 + a_col);
            #pragma unroll
            for (int np = 0; np < 2; np++)
                ldsm_x4(bf[np], bs + (size_t)(b_row + np * 16) * HSM + ks * 16 + b_col);
            #pragma unroll
            for (int mi = 0; mi < 4; mi++)
                #pragma unroll
                for (int ni = 0; ni < 4; ni++)
                    mma_f16(acc[mi][ni], af[mi], &bf[ni >> 1][(ni & 1) * 2]);
        }
    }

    #pragma unroll
    for (int mi = 0; mi < 4; mi++) {
        const int r0 = blockIdx.y * 128 + wm * 64 + mi * 16 + g;
        #pragma unroll
        for (int ni = 0; ni < 4; ni++) {
            const int col = blockIdx.x * 128 + wn * 32 + ni * 8 + t * 2;
            float bv0 = 0.0f, bv1 = 0.0f;
            if (bias != nullptr) { bv0 = bias[col]; bv1 = bias[col + 1]; }
            float r00 = acc[mi][ni][0] + bv0;
            float r01 = acc[mi][ni][1] + bv1;
            float r10 = acc[mi][ni][2] + bv0;
            float r11 = acc[mi][ni][3] + bv1;
            if (OUT_HALF) {
                __half* C = (__half*)Cv;
                *(uint32_t*)(C + (size_t)r0 * ldc + col)       = pack_h2(r00, r01);
                *(uint32_t*)(C + (size_t)(r0 + 8) * ldc + col) = pack_h2(r10, r11);
            } else {
                float* C = (float*)Cv;
                *(float2*)(C + (size_t)r0 * ldc + col)       = make_float2(r00, r01);
                *(float2*)(C + (size_t)(r0 + 8) * ldc + col) = make_float2(r10, r11);
            }
        }
    }
}

// ---------------------------------------------------------------------------
// Fused fp16 flash attention (ex2.approx softmax, R15 config).
//   qblk = qblk_hi - blockIdx.x/16 (heavy-first within the launch).
// ---------------------------------------------------------------------------
#define FSM 136
#define FLASH_SMEM (3 * 128 * FSM * 2)   // 104448 bytes

__global__ void __launch_bounds__(256)
flash_h(const __half* __restrict__ qkv, const uint8_t* __restrict__ mask,
        __half* __restrict__ ctx, int qblk_hi)
{
    const int qblk = qblk_hi - (int)(blockIdx.x >> 4);
    const int head = blockIdx.x & 15;

    extern __shared__ __half smf[];
    __half* Qs = smf;
    __half* Ks = Qs + 128 * FSM;
    __half* Vs = Ks + 128 * FSM;

    const int tid  = threadIdx.x;
    const int w    = tid >> 5;
    const int lane = tid & 31;
    const int g    = lane >> 2;
    const int t    = lane & 3;

    const float inv_norm = 0.08838834764831845f;          // 1/sqrt(128)
    const float LOG2E    = 1.4426950408889634f;
    const float CEXP     = inv_norm * LOG2E;
    const float MASK_RAW = -1.0e9f;

    // ---- Q block ----
    const __half* qsrc = qkv + (size_t)(qblk * 128) * QKV_N + head * 384;
    #pragma unroll
    for (int i = 0; i < 8; i++) {
        int idx = tid + i * 256;
        int r = idx >> 4, sgo = (idx & 15) * 8;
        cp16(Qs + r * FSM + sgo, qsrc + (size_t)r * QKV_N + sgo);
    }
    CP_COMMIT();

    float o[16][4];
    #pragma unroll
    for (int ni = 0; ni < 16; ni++)
        #pragma unroll
        for (int q = 0; q < 4; q++) o[ni][q] = 0.0f;

    float m0 = -1e30f, m1 = -1e30f, l0 = 0.0f, l1 = 0.0f;

    const int row0g = qblk * 128 + w * 16 + g;
    const int row1g = row0g + 8;

    const int qa_row = w * 16 + (lane & 15);
    const int qa_col = (lane >> 4) << 3;
    const int kb_row = ((lane >> 4) << 3) + (lane & 7);
    const int kb_col = ((lane >> 3) & 1) << 3;
    const int vb_row = (((lane >> 3) & 1) << 3) + (lane & 7);
    const int vb_col = (lane >> 4) << 3;

    for (int j = 0; j <= qblk; j++) {
        __syncthreads();
        const __half* ksrc = qkv + (size_t)(j * 128) * QKV_N + head * 384 + 128;
        const __half* vsrc = ksrc + 128;
        #pragma unroll
        for (int i = 0; i < 8; i++) {
            int idx = tid + i * 256;
            int r = idx >> 4, sgo = (idx & 15) * 8;
            cp16(Ks + r * FSM + sgo, ksrc + (size_t)r * QKV_N + sgo);
        }
        CP_COMMIT();                    // K group
        #pragma unroll
        for (int i = 0; i < 8; i++) {
            int idx = tid + i * 256;
            int r = idx >> 4, sgo = (idx & 15) * 8;
            cp16(Vs + r * FSM + sgo, vsrc + (size_t)r * QKV_N + sgo);
        }
        CP_COMMIT();                    // V group

        const int mflag = g_mflag[qblk * 16 + j];

        CP_WAIT(1);
        __syncthreads();

        // ---- S = Q . K^T (raw scores) ----
        float s[16][4];
        #pragma unroll
        for (int ni = 0; ni < 16; ni++)
            #pragma unroll
            for (int q = 0; q < 4; q++) s[ni][q] = 0.0f;

        #pragma unroll
        for (int kk = 0; kk < 8; kk++) {
            uint32_t aq[4];
            ldsm_x4(aq, Qs + (size_t)qa_row * FSM + kk * 16 + qa_col);
            #pragma unroll
            for (int np = 0; np < 8; np++) {
                uint32_t bk[4];
                ldsm_x4(bk, Ks + (size_t)(kb_row + np * 16) * FSM + kk * 16 + kb_col);
                mma_f16(s[2 * np],     aq, bk);
                mma_f16(s[2 * np + 1], aq, bk + 2);
            }
        }

        // ---- masks (raw domain) ----
        if (mflag) {
            const uint8_t* mr0 = mask + (size_t)row0g * SEQ + j * 128;
            const uint8_t* mr1 = mask + (size_t)row1g * SEQ + j * 128;
            #pragma unroll
            for (int ni = 0; ni < 16; ni++) {
                int c = ni * 8 + 2 * t;
                unsigned short mm0 = *(const unsigned short*)(mr0 + c);
                unsigned short mm1 = *(const unsigned short*)(mr1 + c);
                if (mm0 & 0x00FF) s[ni][0] = MASK_RAW;
                if (mm0 & 0xFF00) s[ni][1] = MASK_RAW;
                if (mm1 & 0x00FF) s[ni][2] = MASK_RAW;
                if (mm1 & 0xFF00) s[ni][3] = MASK_RAW;
            }
        }
        if (j == qblk) {
            #pragma unroll
            for (int ni = 0; ni < 16; ni++) {
                int cg = qblk * 128 + ni * 8 + 2 * t;
                if (cg     > row0g) s[ni][0] = -1e30f;
                if (cg + 1 > row0g) s[ni][1] = -1e30f;
                if (cg     > row1g) s[ni][2] = -1e30f;
                if (cg + 1 > row1g) s[ni][3] = -1e30f;
            }
        }

        // ---- online softmax (ex2.approx.f16x2) ----
        float mx0 = -1e30f, mx1 = -1e30f;
        #pragma unroll
        for (int ni = 0; ni < 16; ni++) {
            mx0 = fmaxf(mx0, fmaxf(s[ni][0], s[ni][1]));
            mx1 = fmaxf(mx1, fmaxf(s[ni][2], s[ni][3]));
        }
        mx0 = fmaxf(mx0, __shfl_xor_sync(0xFFFFFFFFu, mx0, 1));
        mx0 = fmaxf(mx0, __shfl_xor_sync(0xFFFFFFFFu, mx0, 2));
        mx1 = fmaxf(mx1, __shfl_xor_sync(0xFFFFFFFFu, mx1, 1));
        mx1 = fmaxf(mx1, __shfl_xor_sync(0xFFFFFFFFu, mx1, 2));

        float mn0 = fmaxf(m0, mx0 * inv_norm);
        float mn1 = fmaxf(m1, mx1 * inv_norm);
        float al0 = __expf(m0 - mn0), al1 = __expf(m1 - mn1);
        m0 = mn0; m1 = mn1;
        const float k0 = mn0 * LOG2E;
        const float k1 = mn1 * LOG2E;

        float sum0 = 0.0f, sum1 = 0.0f;
        #pragma unroll
        for (int ni = 0; ni < 16; ni++) {
            float h0 = fmaf(s[ni][0], CEXP, -k0);
            float h1 = fmaf(s[ni][1], CEXP, -k0);
            float h2 = fmaf(s[ni][2], CEXP, -k1);
            float h3 = fmaf(s[ni][3], CEXP, -k1);
            uint32_t pa = ex2_h2(h0, h1);
            uint32_t pb = ex2_h2(h2, h3);
            __half2 ha = *reinterpret_cast<__half2*>(&pa);
            __half2 hb = *reinterpret_cast<__half2*>(&pb);
            float2 fa = __half22float2(ha);
            float2 fb = __half22float2(hb);
            sum0 += fa.x + fa.y;
            sum1 += fb.x + fb.y;
            s[ni][0] = __uint_as_float(pa);
            s[ni][1] = __uint_as_float(pb);
        }
        sum0 += __shfl_xor_sync(0xFFFFFFFFu, sum0, 1);
        sum0 += __shfl_xor_sync(0xFFFFFFFFu, sum0, 2);
        sum1 += __shfl_xor_sync(0xFFFFFFFFu, sum1, 1);
        sum1 += __shfl_xor_sync(0xFFFFFFFFu, sum1, 2);
        l0 = l0 * al0 + sum0;
        l1 = l1 * al1 + sum1;

        #pragma unroll
        for (int ni = 0; ni < 16; ni++) {
            o[ni][0] *= al0; o[ni][1] *= al0;
            o[ni][2] *= al1; o[ni][3] *= al1;
        }

        CP_WAIT(0);
        __syncthreads();

        // ---- O += P . V ----
        #pragma unroll
        for (int kb = 0; kb < 8; kb++) {
            uint32_t pa[4];
            pa[0] = __float_as_uint(s[2 * kb][0]);
            pa[1] = __float_as_uint(s[2 * kb][1]);
            pa[2] = __float_as_uint(s[2 * kb + 1][0]);
            pa[3] = __float_as_uint(s[2 * kb + 1][1]);
            #pragma unroll
            for (int np = 0; np < 8; np++) {
                uint32_t bv[4];
                ldsm_x4_t(bv, Vs + (size_t)(vb_row + kb * 16) * FSM + np * 16 + vb_col);
                mma_f16(o[2 * np],     pa, bv);
                mma_f16(o[2 * np + 1], pa, bv + 2);
            }
        }
    }

    // ---- epilogue ----
    const float il0 = 1.0f / l0;
    const float il1 = 1.0f / l1;
    __half* c0 = ctx + (size_t)row0g * HID + head * HDIM;
    __half* c1 = ctx + (size_t)row1g * HID + head * HDIM;
    #pragma unroll
    for (int ni = 0; ni < 16; ni++) {
        int c = ni * 8 + 2 * t;
        *(uint32_t*)(c0 + c) = pack_h2(o[ni][0] * il0, o[ni][1] * il0);
        *(uint32_t*)(c1 + c) = pack_h2(o[ni][2] * il1, o[ni][3] * il1);
    }
}

__global__ void copy_bias(const float* __restrict__ b, float* __restrict__ out)
{
    int i = blockIdx.x * 256 + threadIdx.x;
    if (i < HID) out[i] = b[i];
}

// ============================================================================
extern "C" void kernel_launch(void* const* d_in, const int* in_sizes, int n_in,
                              void* d_out, int out_size)
{
    const float*   hs     = (const float*)d_in[0];
    const float*   w_qkv  = (const float*)d_in[1];
    const float*   b_qkv  = (const float*)d_in[2];
    const float*   w_proj = (const float*)d_in[3];
    const float*   b_proj = (const float*)d_in[4];
    const uint8_t* mask   = (const uint8_t*)d_in[5];

    __half *qkv, *ctx, *phs, *pwqkv, *pwproj;
    cudaGetSymbolAddress((void**)&qkv,    g_qkv);
    cudaGetSymbolAddress((void**)&ctx,    g_ctx);
    cudaGetSymbolAddress((void**)&phs,    g_hs);
    cudaGetSymbolAddress((void**)&pwqkv,  g_wqkv);
    cudaGetSymbolAddress((void**)&pwproj, g_wproj);
    float* out = (float*)d_out;

    static bool attr_set = false;
    static cudaStream_t s1 = nullptr;
    static cudaEvent_t eFork = nullptr, eSide = nullptr, eQKV = nullptr, eS1 = nullptr;
    if (!attr_set) {
        cudaFuncSetAttribute(flash_h, cudaFuncAttributeMaxDynamicSharedMemorySize, FLASH_SMEM);
        cudaFuncSetAttribute(gemm_h<true>,  cudaFuncAttributeMaxDynamicSharedMemorySize, GEMM_SMEM);
        cudaFuncSetAttribute(gemm_h<false>, cudaFuncAttributeMaxDynamicSharedMemorySize, GEMM_SMEM);
        cudaStreamCreateWithFlags(&s1, cudaStreamNonBlocking);
        cudaEventCreateWithFlags(&eFork, cudaEventDisableTiming);
        cudaEventCreateWithFlags(&eSide, cudaEventDisableTiming);
        cudaEventCreateWithFlags(&eQKV,  cudaEventDisableTiming);
        cudaEventCreateWithFlags(&eS1,   cudaEventDisableTiming);
        attr_set = true;
    }

    const int N4_HS    = SEQ * HID / 4;
    const int N4_WQKV  = QKV_N * HID / 4;
    const int N4_WPROJ = HID * HID / 4;

    // ---- fork: side stream runs hs-prep + QKV-independent work ----
    cudaEventRecord(eFork, 0);
    cudaStreamWaitEvent(s1, eFork, 0);
    prep_h<<<(N4_HS + 1023) / 1024, 256, 0, s1>>>(hs, phs, N4_HS);
    prep_h<<<(N4_WPROJ + 1023) / 1024, 256, 0, s1>>>(w_proj, pwproj, N4_WPROJ);
    mask_reduce<<<dim3(16, 16), 256, 0, s1>>>(mask);
    if (out_size >= SEQ * HID + HID) {
        copy_bias<<<(HID + 255) / 256, 256, 0, s1>>>(b_proj, out + (size_t)SEQ * HID);
    }
    cudaEventRecord(eSide, s1);

    // ---- main: wqkv prep (co-runs with side), then QKV ----
    prep_h<<<(N4_WQKV + 1023) / 1024, 256>>>(w_qkv, pwqkv, N4_WQKV);
    cudaStreamWaitEvent(0, eSide, 0);

    gemm_h<true><<<dim3(QKV_N / 128, SEQ / 128), 256, GEMM_SMEM>>>(
        phs, HID, pwqkv, HID, qkv, QKV_N, b_qkv, HID);
    cudaEventRecord(eQKV, 0);

    // ---- main: flash_hi (qblk 8..15, long chains) ----
    flash_h<<<dim3(8 * NHEAD), 256, FLASH_SMEM>>>(qkv, mask, ctx, 15);

    // ---- side: flash_lo (qblk 0..7, short chains) -> proj_low backfills ----
    cudaStreamWaitEvent(s1, eQKV, 0);
    flash_h<<<dim3(8 * NHEAD), 256, FLASH_SMEM, s1>>>(qkv, mask, ctx, 7);
    gemm_h<false><<<dim3(HID / 128, 8), 256, GEMM_SMEM, s1>>>(
        ctx, HID, pwproj, HID, out, HID, nullptr, HID);
    cudaEventRecord(eS1, s1);

    // ---- main: proj_high (rows 1024..2047) after flash_hi; join side ----
    gemm_h<false><<<dim3(HID / 128, 8), 256, GEMM_SMEM>>>(
        ctx + (size_t)1024 * HID, HID, pwproj, HID,
        out + (size_t)1024 * HID, HID, nullptr, HID);
    cudaStreamWaitEvent(0, eS1, 0);
}

// round 17
// speedup vs baseline: 1.0166x; 1.0166x over previous
#include <cuda_runtime.h>
#include <cuda_fp16.h>
#include <math.h>
#include <stdint.h>

// Problem constants (fixed shapes from reference)
#define SEQ   2048
#define HID   2048
#define NHEAD 16
#define HDIM  128
#define QKV_N (3 * HID)   // 6144

// -------- device scratch (static; no allocations allowed) --------
__device__ __half g_qkv[SEQ * QKV_N];     // [s, 3h] QKV output (fp16)
__device__ __half g_ctx[SEQ * HID];       // [s, h] context (fp16)
__device__ __half g_hs[SEQ * HID];        // fp16 hidden_states
__device__ __half g_wqkv[QKV_N * HID];    // fp16 w_qkv
__device__ __half g_wproj[HID * HID];     // fp16 w_proj
__device__ int    g_mflag[16 * 16];       // per-128x128-tile mask OR flags

// ---------------------------------------------------------------------------
// helpers
// ---------------------------------------------------------------------------
__device__ __forceinline__ uint32_t pack_h2(float lo, float hi) {
    __half2 h = __floats2half2_rn(lo, hi);
    return *reinterpret_cast<uint32_t*>(&h);
}

__device__ __forceinline__ uint32_t ex2_h2(float lo, float hi) {
    __half2 h = __floats2half2_rn(lo, hi);
    uint32_t x = *reinterpret_cast<uint32_t*>(&h);
    uint32_t r;
    asm("ex2.approx.f16x2 %0, %1;" : "=r"(r) : "r"(x));
    return r;
}

__device__ __forceinline__ void mma_f16(float* d, const uint32_t* a, const uint32_t* b) {
    asm volatile(
        "mma.sync.aligned.m16n8k16.row.col.f32.f16.f16.f32 "
        "{%0,%1,%2,%3}, {%4,%5,%6,%7}, {%8,%9}, {%0,%1,%2,%3};"
        : "+f"(d[0]), "+f"(d[1]), "+f"(d[2]), "+f"(d[3])
        : "r"(a[0]), "r"(a[1]), "r"(a[2]), "r"(a[3]), "r"(b[0]), "r"(b[1]));
}

__device__ __forceinline__ void ldsm_x4(uint32_t* r, const void* p) {
    uint32_t a = (uint32_t)__cvta_generic_to_shared(p);
    asm volatile("ldmatrix.sync.aligned.m8n8.x4.shared.b16 {%0,%1,%2,%3}, [%4];"
        : "=r"(r[0]), "=r"(r[1]), "=r"(r[2]), "=r"(r[3]) : "r"(a));
}

__device__ __forceinline__ void ldsm_x4_t(uint32_t* r, const void* p) {
    uint32_t a = (uint32_t)__cvta_generic_to_shared(p);
    asm volatile("ldmatrix.sync.aligned.m8n8.x4.trans.shared.b16 {%0,%1,%2,%3}, [%4];"
        : "=r"(r[0]), "=r"(r[1]), "=r"(r[2]), "=r"(r[3]) : "r"(a));
}

__device__ __forceinline__ void cp16(void* dst_smem, const void* src) {
    uint32_t d = (uint32_t)__cvta_generic_to_shared(dst_smem);
    asm volatile("cp.async.cg.shared.global [%0], [%1], 16;" :: "r"(d), "l"(src));
}
#define CP_COMMIT() asm volatile("cp.async.commit_group;" ::: "memory")
#define CP_WAIT(N)  asm volatile("cp.async.wait_group %0;" :: "n"(N) : "memory")

// ---------------------------------------------------------------------------
// fp32 -> fp16 conversion, MLP=4
// ---------------------------------------------------------------------------
__global__ void __launch_bounds__(256)
prep_h(const float* __restrict__ src, __half* __restrict__ dst, int n4)
{
    int base = blockIdx.x * 1024 + threadIdx.x;
    float4 v[4];
    #pragma unroll
    for (int i = 0; i < 4; i++) {
        int idx = base + i * 256;
        if (idx < n4) v[i] = ((const float4*)src)[idx];
    }
    #pragma unroll
    for (int i = 0; i < 4; i++) {
        int idx = base + i * 256;
        if (idx < n4)
            ((uint2*)dst)[idx] = make_uint2(pack_h2(v[i].x, v[i].y),
                                            pack_h2(v[i].z, v[i].w));
    }
}

// ---------------------------------------------------------------------------
// mask tile OR-reduction
// ---------------------------------------------------------------------------
__global__ void __launch_bounds__(256)
mask_reduce(const uint8_t* __restrict__ mask)
{
    const int qt = blockIdx.y, kt = blockIdx.x;
    const uint8_t* base = mask + (size_t)(qt * 128) * SEQ + kt * 128;
    uint32_t acc = 0;
    #pragma unroll
    for (int i = 0; i < 4; i++) {
        int idx = threadIdx.x + i * 256;
        int r = idx >> 3, c = (idx & 7) * 16;
        uint4 v = *(const uint4*)(base + (size_t)r * SEQ + c);
        acc |= v.x | v.y | v.z | v.w;
    }
    int any = __syncthreads_or((int)(acc != 0));
    if (threadIdx.x == 0) g_mflag[qt * 16 + kt] = any;
}

// ---------------------------------------------------------------------------
// fp16 mma.sync GEMM (round-7 config, best known)
// ---------------------------------------------------------------------------
#define HSM 72
#define GSTG 3
#define GEMM_SMEM (GSTG * 2 * 128 * HSM * 2)   // 110592 bytes

template<bool OUT_HALF>
__global__ void __launch_bounds__(256, 2)
gemm_h(const __half* __restrict__ A, int lda,
       const __half* __restrict__ B, int ldb,
       void* __restrict__ Cv, int ldc,
       const float* __restrict__ bias, int K)
{
    extern __shared__ __half smh[];
    __half* As = smh;
    __half* Bs = smh + GSTG * 128 * HSM;

    const int tid = threadIdx.x;
    const int wid = tid >> 5;
    const int lane = tid & 31;
    const int t = lane & 3;
    const int g = lane >> 2;
    const int wm = wid & 1;
    const int wn = wid >> 1;

    A += (size_t)(blockIdx.y * 128) * lda;
    B += (size_t)(blockIdx.x * 128) * ldb;

    float acc[4][4][4];
    #pragma unroll
    for (int mi = 0; mi < 4; mi++)
        #pragma unroll
        for (int ni = 0; ni < 4; ni++)
            #pragma unroll
            for (int q = 0; q < 4; q++) acc[mi][ni][q] = 0.0f;

    const int nch = K >> 6;

    auto issue = [&](int st, int k0) {
        __half* as = As + st * 128 * HSM;
        __half* bs = Bs + st * 128 * HSM;
        #pragma unroll
        for (int i = 0; i < 4; i++) {
            int idx = tid + i * 256;
            int r = idx >> 3;
            int sgo = (idx & 7) * 8;
            cp16(as + r * HSM + sgo, A + (size_t)r * lda + k0 + sgo);
            cp16(bs + r * HSM + sgo, B + (size_t)r * ldb + k0 + sgo);
        }
        CP_COMMIT();
    };

    issue(0, 0);
    if (nch > 1) issue(1, 64);

    const int a_row = wm * 64 + (lane & 15);
    const int a_col = (lane >> 4) << 3;
    const int b_row = wn * 32 + ((lane >> 4) << 3) + (lane & 7);
    const int b_col = ((lane >> 3) & 1) << 3;

    for (int c = 0; c < nch; c++) {
        if (c + 1 < nch) { CP_WAIT(1); } else { CP_WAIT(0); }
        __syncthreads();
        if (c + 2 < nch) issue((c + 2) % GSTG, (c + 2) * 64);

        const __half* as = As + (c % GSTG) * 128 * HSM;
        const __half* bs = Bs + (c % GSTG) * 128 * HSM;
        #pragma unroll
        for (int ks = 0; ks < 4; ks++) {
            uint32_t af[4][4], bf[2][4];
            #pragma unroll
            for (int mi = 0; mi < 4; mi++)
                ldsm_x4(af[mi], as + (size_t)(a_row + mi * 16) * HSM + ks * 16 + a_col);
            #pragma unroll
            for (int np = 0; np < 2; np++)
                ldsm_x4(bf[np], bs + (size_t)(b_row + np * 16) * HSM + ks * 16 + b_col);
            #pragma unroll
            for (int mi = 0; mi < 4; mi++)
                #pragma unroll
                for (int ni = 0; ni < 4; ni++)
                    mma_f16(acc[mi][ni], af[mi], &bf[ni >> 1][(ni & 1) * 2]);
        }
    }

    #pragma unroll
    for (int mi = 0; mi < 4; mi++) {
        const int r0 = blockIdx.y * 128 + wm * 64 + mi * 16 + g;
        #pragma unroll
        for (int ni = 0; ni < 4; ni++) {
            const int col = blockIdx.x * 128 + wn * 32 + ni * 8 + t * 2;
            float bv0 = 0.0f, bv1 = 0.0f;
            if (bias != nullptr) { bv0 = bias[col]; bv1 = bias[col + 1]; }
            float r00 = acc[mi][ni][0] + bv0;
            float r01 = acc[mi][ni][1] + bv1;
            float r10 = acc[mi][ni][2] + bv0;
            float r11 = acc[mi][ni][3] + bv1;
            if (OUT_HALF) {
                __half* C = (__half*)Cv;
                *(uint32_t*)(C + (size_t)r0 * ldc + col)       = pack_h2(r00, r01);
                *(uint32_t*)(C + (size_t)(r0 + 8) * ldc + col) = pack_h2(r10, r11);
            } else {
                float* C = (float*)Cv;
                *(float2*)(C + (size_t)r0 * ldc + col)       = make_float2(r00, r01);
                *(float2*)(C + (size_t)(r0 + 8) * ldc + col) = make_float2(r10, r11);
            }
        }
    }
}

// ---------------------------------------------------------------------------
// Fused fp16 flash attention (ex2.approx softmax, R15 config).
// ---------------------------------------------------------------------------
#define FSM 136
#define FLASH_SMEM (3 * 128 * FSM * 2)   // 104448 bytes

__global__ void __launch_bounds__(256)
flash_h(const __half* __restrict__ qkv, const uint8_t* __restrict__ mask,
        __half* __restrict__ ctx)
{
    const int qblk = 15 - (int)(blockIdx.x >> 4);   // heavy CTAs first
    const int head = blockIdx.x & 15;

    extern __shared__ __half smf[];
    __half* Qs = smf;
    __half* Ks = Qs + 128 * FSM;
    __half* Vs = Ks + 128 * FSM;

    const int tid  = threadIdx.x;
    const int w    = tid >> 5;
    const int lane = tid & 31;
    const int g    = lane >> 2;
    const int t    = lane & 3;

    const float inv_norm = 0.08838834764831845f;          // 1/sqrt(128)
    const float LOG2E    = 1.4426950408889634f;
    const float CEXP     = inv_norm * LOG2E;
    const float MASK_RAW = -1.0e9f;

    // ---- Q block ----
    const __half* qsrc = qkv + (size_t)(qblk * 128) * QKV_N + head * 384;
    #pragma unroll
    for (int i = 0; i < 8; i++) {
        int idx = tid + i * 256;
        int r = idx >> 4, sgo = (idx & 15) * 8;
        cp16(Qs + r * FSM + sgo, qsrc + (size_t)r * QKV_N + sgo);
    }
    CP_COMMIT();

    float o[16][4];
    #pragma unroll
    for (int ni = 0; ni < 16; ni++)
        #pragma unroll
        for (int q = 0; q < 4; q++) o[ni][q] = 0.0f;

    float m0 = -1e30f, m1 = -1e30f, l0 = 0.0f, l1 = 0.0f;

    const int row0g = qblk * 128 + w * 16 + g;
    const int row1g = row0g + 8;

    const int qa_row = w * 16 + (lane & 15);
    const int qa_col = (lane >> 4) << 3;
    const int kb_row = ((lane >> 4) << 3) + (lane & 7);
    const int kb_col = ((lane >> 3) & 1) << 3;
    const int vb_row = (((lane >> 3) & 1) << 3) + (lane & 7);
    const int vb_col = (lane >> 4) << 3;

    for (int j = 0; j <= qblk; j++) {
        __syncthreads();
        const __half* ksrc = qkv + (size_t)(j * 128) * QKV_N + head * 384 + 128;
        const __half* vsrc = ksrc + 128;
        #pragma unroll
        for (int i = 0; i < 8; i++) {
            int idx = tid + i * 256;
            int r = idx >> 4, sgo = (idx & 15) * 8;
            cp16(Ks + r * FSM + sgo, ksrc + (size_t)r * QKV_N + sgo);
        }
        CP_COMMIT();                    // K group
        #pragma unroll
        for (int i = 0; i < 8; i++) {
            int idx = tid + i * 256;
            int r = idx >> 4, sgo = (idx & 15) * 8;
            cp16(Vs + r * FSM + sgo, vsrc + (size_t)r * QKV_N + sgo);
        }
        CP_COMMIT();                    // V group

        const int mflag = g_mflag[qblk * 16 + j];

        CP_WAIT(1);
        __syncthreads();

        // ---- S = Q . K^T (raw scores) ----
        float s[16][4];
        #pragma unroll
        for (int ni = 0; ni < 16; ni++)
            #pragma unroll
            for (int q = 0; q < 4; q++) s[ni][q] = 0.0f;

        #pragma unroll
        for (int kk = 0; kk < 8; kk++) {
            uint32_t aq[4];
            ldsm_x4(aq, Qs + (size_t)qa_row * FSM + kk * 16 + qa_col);
            #pragma unroll
            for (int np = 0; np < 8; np++) {
                uint32_t bk[4];
                ldsm_x4(bk, Ks + (size_t)(kb_row + np * 16) * FSM + kk * 16 + kb_col);
                mma_f16(s[2 * np],     aq, bk);
                mma_f16(s[2 * np + 1], aq, bk + 2);
            }
        }

        // ---- masks (raw domain) ----
        if (mflag) {
            const uint8_t* mr0 = mask + (size_t)row0g * SEQ + j * 128;
            const uint8_t* mr1 = mask + (size_t)row1g * SEQ + j * 128;
            #pragma unroll
            for (int ni = 0; ni < 16; ni++) {
                int c = ni * 8 + 2 * t;
                unsigned short mm0 = *(const unsigned short*)(mr0 + c);
                unsigned short mm1 = *(const unsigned short*)(mr1 + c);
                if (mm0 & 0x00FF) s[ni][0] = MASK_RAW;
                if (mm0 & 0xFF00) s[ni][1] = MASK_RAW;
                if (mm1 & 0x00FF) s[ni][2] = MASK_RAW;
                if (mm1 & 0xFF00) s[ni][3] = MASK_RAW;
            }
        }
        if (j == qblk) {
            #pragma unroll
            for (int ni = 0; ni < 16; ni++) {
                int cg = qblk * 128 + ni * 8 + 2 * t;
                if (cg     > row0g) s[ni][0] = -1e30f;
                if (cg + 1 > row0g) s[ni][1] = -1e30f;
                if (cg     > row1g) s[ni][2] = -1e30f;
                if (cg + 1 > row1g) s[ni][3] = -1e30f;
            }
        }

        // ---- online softmax (ex2.approx.f16x2) ----
        float mx0 = -1e30f, mx1 = -1e30f;
        #pragma unroll
        for (int ni = 0; ni < 16; ni++) {
            mx0 = fmaxf(mx0, fmaxf(s[ni][0], s[ni][1]));
            mx1 = fmaxf(mx1, fmaxf(s[ni][2], s[ni][3]));
        }
        mx0 = fmaxf(mx0, __shfl_xor_sync(0xFFFFFFFFu, mx0, 1));
        mx0 = fmaxf(mx0, __shfl_xor_sync(0xFFFFFFFFu, mx0, 2));
        mx1 = fmaxf(mx1, __shfl_xor_sync(0xFFFFFFFFu, mx1, 1));
        mx1 = fmaxf(mx1, __shfl_xor_sync(0xFFFFFFFFu, mx1, 2));

        float mn0 = fmaxf(m0, mx0 * inv_norm);
        float mn1 = fmaxf(m1, mx1 * inv_norm);
        float al0 = __expf(m0 - mn0), al1 = __expf(m1 - mn1);
        m0 = mn0; m1 = mn1;
        const float k0 = mn0 * LOG2E;
        const float k1 = mn1 * LOG2E;

        float sum0 = 0.0f, sum1 = 0.0f;
        #pragma unroll
        for (int ni = 0; ni < 16; ni++) {
            float h0 = fmaf(s[ni][0], CEXP, -k0);
            float h1 = fmaf(s[ni][1], CEXP, -k0);
            float h2 = fmaf(s[ni][2], CEXP, -k1);
            float h3 = fmaf(s[ni][3], CEXP, -k1);
            uint32_t pa = ex2_h2(h0, h1);
            uint32_t pb = ex2_h2(h2, h3);
            __half2 ha = *reinterpret_cast<__half2*>(&pa);
            __half2 hb = *reinterpret_cast<__half2*>(&pb);
            float2 fa = __half22float2(ha);
            float2 fb = __half22float2(hb);
            sum0 += fa.x + fa.y;
            sum1 += fb.x + fb.y;
            s[ni][0] = __uint_as_float(pa);
            s[ni][1] = __uint_as_float(pb);
        }
        sum0 += __shfl_xor_sync(0xFFFFFFFFu, sum0, 1);
        sum0 += __shfl_xor_sync(0xFFFFFFFFu, sum0, 2);
        sum1 += __shfl_xor_sync(0xFFFFFFFFu, sum1, 1);
        sum1 += __shfl_xor_sync(0xFFFFFFFFu, sum1, 2);
        l0 = l0 * al0 + sum0;
        l1 = l1 * al1 + sum1;

        #pragma unroll
        for (int ni = 0; ni < 16; ni++) {
            o[ni][0] *= al0; o[ni][1] *= al0;
            o[ni][2] *= al1; o[ni][3] *= al1;
        }

        CP_WAIT(0);
        __syncthreads();

        // ---- O += P . V ----
        #pragma unroll
        for (int kb = 0; kb < 8; kb++) {
            uint32_t pa[4];
            pa[0] = __float_as_uint(s[2 * kb][0]);
            pa[1] = __float_as_uint(s[2 * kb][1]);
            pa[2] = __float_as_uint(s[2 * kb + 1][0]);
            pa[3] = __float_as_uint(s[2 * kb + 1][1]);
            #pragma unroll
            for (int np = 0; np < 8; np++) {
                uint32_t bv[4];
                ldsm_x4_t(bv, Vs + (size_t)(vb_row + kb * 16) * FSM + np * 16 + vb_col);
                mma_f16(o[2 * np],     pa, bv);
                mma_f16(o[2 * np + 1], pa, bv + 2);
            }
        }
    }

    // ---- epilogue ----
    const float il0 = 1.0f / l0;
    const float il1 = 1.0f / l1;
    __half* c0 = ctx + (size_t)row0g * HID + head * HDIM;
    __half* c1 = ctx + (size_t)row1g * HID + head * HDIM;
    #pragma unroll
    for (int ni = 0; ni < 16; ni++) {
        int c = ni * 8 + 2 * t;
        *(uint32_t*)(c0 + c) = pack_h2(o[ni][0] * il0, o[ni][1] * il0);
        *(uint32_t*)(c1 + c) = pack_h2(o[ni][2] * il1, o[ni][3] * il1);
    }
}

__global__ void copy_bias(const float* __restrict__ b, float* __restrict__ out)
{
    int i = blockIdx.x * 256 + threadIdx.x;
    if (i < HID) out[i] = b[i];
}

// ============================================================================
extern "C" void kernel_launch(void* const* d_in, const int* in_sizes, int n_in,
                              void* d_out, int out_size)
{
    const float*   hs     = (const float*)d_in[0];
    const float*   w_qkv  = (const float*)d_in[1];
    const float*   b_qkv  = (const float*)d_in[2];
    const float*   w_proj = (const float*)d_in[3];
    const float*   b_proj = (const float*)d_in[4];
    const uint8_t* mask   = (const uint8_t*)d_in[5];

    __half *qkv, *ctx, *phs, *pwqkv, *pwproj;
    cudaGetSymbolAddress((void**)&qkv,    g_qkv);
    cudaGetSymbolAddress((void**)&ctx,    g_ctx);
    cudaGetSymbolAddress((void**)&phs,    g_hs);
    cudaGetSymbolAddress((void**)&pwqkv,  g_wqkv);
    cudaGetSymbolAddress((void**)&pwproj, g_wproj);
    float* out = (float*)d_out;

    static bool attr_set = false;
    static cudaStream_t s1 = nullptr;
    static cudaEvent_t eFork = nullptr, eHS = nullptr, eSide = nullptr;
    if (!attr_set) {
        cudaFuncSetAttribute(flash_h, cudaFuncAttributeMaxDynamicSharedMemorySize, FLASH_SMEM);
        cudaFuncSetAttribute(gemm_h<true>,  cudaFuncAttributeMaxDynamicSharedMemorySize, GEMM_SMEM);
        cudaFuncSetAttribute(gemm_h<false>, cudaFuncAttributeMaxDynamicSharedMemorySize, GEMM_SMEM);
        cudaStreamCreateWithFlags(&s1, cudaStreamNonBlocking);
        cudaEventCreateWithFlags(&eFork, cudaEventDisableTiming);
        cudaEventCreateWithFlags(&eHS,   cudaEventDisableTiming);
        cudaEventCreateWithFlags(&eSide, cudaEventDisableTiming);
        attr_set = true;
    }

    const int N4_HS    = SEQ * HID / 4;
    const int N4_WQKV  = QKV_N * HID / 4;
    const int N4_WPROJ = HID * HID / 4;

    // ---- fork: side stream. QKV needs only prep_hs from here. ----
    cudaEventRecord(eFork, 0);
    cudaStreamWaitEvent(s1, eFork, 0);
    prep_h<<<(N4_HS + 1023) / 1024, 256, 0, s1>>>(hs, phs, N4_HS);
    cudaEventRecord(eHS, s1);                       // QKV gate
    prep_h<<<(N4_WPROJ + 1023) / 1024, 256, 0, s1>>>(w_proj, pwproj, N4_WPROJ);
    mask_reduce<<<dim3(16, 16), 256, 0, s1>>>(mask);
    if (out_size >= SEQ * HID + HID) {
        copy_bias<<<(HID + 255) / 256, 256, 0, s1>>>(b_proj, out + (size_t)SEQ * HID);
    }
    cudaEventRecord(eSide, s1);                     // flash/proj gate

    // ---- main: wqkv prep; QKV waits only on prep_hs ----
    prep_h<<<(N4_WQKV + 1023) / 1024, 256>>>(w_qkv, pwqkv, N4_WQKV);
    cudaStreamWaitEvent(0, eHS, 0);

    gemm_h<true><<<dim3(QKV_N / 128, SEQ / 128), 256, GEMM_SMEM>>>(
        phs, HID, pwqkv, HID, qkv, QKV_N, b_qkv, HID);

    // wproj/mask/bias finished long ago (ran under QKV); join before use
    cudaStreamWaitEvent(0, eSide, 0);

    flash_h<<<dim3(16 * NHEAD), 256, FLASH_SMEM>>>(qkv, mask, ctx);

    gemm_h<false><<<dim3(HID / 128, SEQ / 128), 256, GEMM_SMEM>>>(
        ctx, HID, pwproj, HID, out, HID, nullptr, HID);
}